// round 15
// baseline (speedup 1.0000x reference)
#include <cuda_runtime.h>
#include <cuda.h>
#include <cuda_fp16.h>
#include <cstdint>

// ================= problem constants =================
#define BS      65536
#define DDIM    768
#define NHEAD   12
#define CPT     6                   // chunks per tile (768/128)
#define NTILES  6144                // (BS/128) * NHEAD
#define GRID    148
#define NTHREADS 416                // 12 consumer warps + 1 producer warp
#define SUB_BYTES 40960             // one 64-K subtile: A 16K + 3x8K W
#define STAGE_BYTES (2 * SUB_BYTES) // 81920 (128-K chunk)
#define NSTAGE  2
#define BUF_OFF (NSTAGE * STAGE_BYTES)           // 163840
#define BUF_STRIDE 72                            // halves per row (144B)
#define BUF_BYTES (128 * BUF_STRIDE * 2)         // 18432 per matrix
#define CTRL_OFF (BUF_OFF + 2 * BUF_BYTES)       // 200704 (q,k bufs only)
#define SMEM_BYTES (CTRL_OFF + 128)              // 200832

// ================= static device scratch (allowed) =================
__device__ __align__(128) __half g_xn2[(size_t)BS * DDIM];   // fp16 LN output
__device__ __align__(128) __half g_w2[3][DDIM * DDIM];       // fp16 Wq,Wk,Wv

// ================= helpers =================
__device__ __forceinline__ uint32_t smem_u32(const void* p) {
    uint32_t a;
    asm("{ .reg .u64 t; cvta.to.shared.u64 t, %1; cvt.u32.u64 %0, t; }" : "=r"(a) : "l"(p));
    return a;
}
__device__ __forceinline__ void ldm4(uint32_t* d, uint32_t addr) {
    asm volatile("ldmatrix.sync.aligned.m8n8.x4.shared.b16 {%0,%1,%2,%3}, [%4];"
                 : "=r"(d[0]), "=r"(d[1]), "=r"(d[2]), "=r"(d[3]) : "r"(addr));
}
__device__ __forceinline__ void hmma(float* c, const uint32_t* a, uint32_t b0, uint32_t b1) {
    asm volatile(
        "mma.sync.aligned.m16n8k16.row.col.f32.f16.f16.f32 "
        "{%0,%1,%2,%3},{%4,%5,%6,%7},{%8,%9},{%0,%1,%2,%3};"
        : "+f"(c[0]), "+f"(c[1]), "+f"(c[2]), "+f"(c[3])
        : "r"(a[0]), "r"(a[1]), "r"(a[2]), "r"(a[3]), "r"(b0), "r"(b1));
}
__device__ __forceinline__ void mbar_init(uint32_t addr, uint32_t cnt) {
    asm volatile("mbarrier.init.shared.b64 [%0], %1;" :: "r"(addr), "r"(cnt) : "memory");
}
__device__ __forceinline__ void mbar_arrive(uint32_t addr) {
    asm volatile("mbarrier.arrive.shared.b64 _, [%0];" :: "r"(addr) : "memory");
}
__device__ __forceinline__ void mbar_expect_tx(uint32_t addr, uint32_t bytes) {
    asm volatile("mbarrier.arrive.expect_tx.shared.b64 _, [%0], %1;"
                 :: "r"(addr), "r"(bytes) : "memory");
}
__device__ __forceinline__ void mbar_wait(uint32_t addr, uint32_t parity) {
    asm volatile(
        "{\n\t.reg .pred P;\n\t"
        "WAITLP_%=:\n\t"
        "mbarrier.try_wait.parity.acquire.cta.shared::cta.b64 P, [%0], %1, 0x989680;\n\t"
        "@!P bra WAITLP_%=;\n\t}"
        :: "r"(addr), "r"(parity) : "memory");
}
__device__ __forceinline__ void tma2d(const CUtensorMap* m, uint32_t dst,
                                      int cx, int cy, uint32_t bar) {
    asm volatile(
        "cp.async.bulk.tensor.2d.shared::cta.global.tile.mbarrier::complete_tx::bytes "
        "[%0], [%1, {%2, %3}], [%4];"
        :: "r"(dst), "l"(m), "r"(cx), "r"(cy), "r"(bar) : "memory");
}
#define FENCE_PROXY() asm volatile("fence.proxy.async.shared::cta;" ::: "memory")
#define CONSUMER_BAR() asm volatile("bar.sync 1, 384;" ::: "memory")

// ================= kernel 0: fused W->fp16 conversion + layernorm ==========
__global__ void __launch_bounds__(256) prep_kernel(const float* __restrict__ x,
                                                   const float* __restrict__ wq,
                                                   const float* __restrict__ wk,
                                                   const float* __restrict__ wv,
                                                   const float* __restrict__ gamma,
                                                   const float* __restrict__ beta) {
    if (blockIdx.x < 576) {
        int i = blockIdx.x * 256 + threadIdx.x;
        const float* srcs[3] = {wq, wk, wv};
#pragma unroll
        for (int m = 0; m < 3; m++) {
            float4 v = ((const float4*)srcs[m])[i];
            union { __half2 h[2]; uint2 u; } cvt;
            cvt.h[0] = __floats2half2_rn(v.x, v.y);
            cvt.h[1] = __floats2half2_rn(v.z, v.w);
            ((uint2*)g_w2[m])[i] = cvt.u;
        }
        return;
    }
    const int row  = (blockIdx.x - 576) * 8 + (threadIdx.x >> 5);
    const int lane = threadIdx.x & 31;
    const float4* xr = (const float4*)(x + (size_t)row * DDIM);
    float4 v[6];
    float s = 0.f;
#pragma unroll
    for (int i = 0; i < 6; i++) {
        v[i] = xr[lane + 32 * i];
        s += v[i].x + v[i].y + v[i].z + v[i].w;
    }
#pragma unroll
    for (int o = 16; o; o >>= 1) s += __shfl_xor_sync(0xffffffffu, s, o);
    const float mu = s * (1.0f / 768.0f);
    float ss = 0.f;
#pragma unroll
    for (int i = 0; i < 6; i++) {
        float a = v[i].x - mu, b = v[i].y - mu, c = v[i].z - mu, d = v[i].w - mu;
        ss += a * a + b * b + c * c + d * d;
    }
#pragma unroll
    for (int o = 16; o; o >>= 1) ss += __shfl_xor_sync(0xffffffffu, ss, o);
    const float inv = rsqrtf(ss * (1.0f / 768.0f) + 1e-6f);
    const float4* g4 = (const float4*)gamma;
    const float4* b4 = (const float4*)beta;
    uint2* dst = (uint2*)(g_xn2 + (size_t)row * DDIM);
#pragma unroll
    for (int i = 0; i < 6; i++) {
        float4 g = g4[lane + 32 * i];
        float4 bb = b4[lane + 32 * i];
        union { __half2 h[2]; uint2 u; } cvt;
        cvt.h[0] = __floats2half2_rn((v[i].x - mu) * inv * g.x + bb.x,
                                     (v[i].y - mu) * inv * g.y + bb.y);
        cvt.h[1] = __floats2half2_rn((v[i].z - mu) * inv * g.z + bb.z,
                                     (v[i].w - mu) * inv * g.w + bb.w);
        dst[lane + 32 * i] = cvt.u;
    }
}

// chunk index -> (k0, row0, col0); chunk covers 128 K-columns
__device__ __forceinline__ void coords(int bid, int l, int& k0, int& row0, int& col0) {
    int tl = l / CPT;
    int c  = l - tl * CPT;
    int t  = bid + GRID * tl;
    int rb = t / NHEAD;
    k0   = c * 128;
    row0 = rb * 128;
    col0 = (t - rb * NHEAD) * 64;
}

// ================= kernel 1: persistent fused QKV GEMM + attention =========
__global__ void __launch_bounds__(NTHREADS, 1) attn_kernel(
        const float* __restrict__ x, float* __restrict__ out,
        const __grid_constant__ CUtensorMap mA,
        const __grid_constant__ CUtensorMap mQ,
        const __grid_constant__ CUtensorMap mK,
        const __grid_constant__ CUtensorMap mV) {
    extern __shared__ __align__(1024) char smem[];
    const uint32_t sb = smem_u32(smem);
    const int tid  = threadIdx.x;
    const int wid  = tid >> 5;
    const int lane = tid & 31;
    const int bid  = blockIdx.x;

    const int ntiles = 41 + (bid < (NTILES - 41 * GRID) ? 1 : 0);  // 76 CTAs get 42
    const int L = ntiles * CPT;

    const uint32_t fullb  = sb + CTRL_OFF;        // 2 full barriers
    const uint32_t emptyb = sb + CTRL_OFF + 16;   // 2 empty barriers

    __half* qbuf = (__half*)(smem + BUF_OFF);
    __half* kbuf = qbuf + 128 * BUF_STRIDE;

    if (tid == 0) {
#pragma unroll
        for (int s = 0; s < NSTAGE; s++) {
            mbar_init(fullb  + 8u * s, 1);
            mbar_init(emptyb + 8u * s, 12);
        }
        FENCE_PROXY();
    }
    __syncthreads();   // only CTA-wide barrier; roles split below

    if (wid == 12) {
        // ================= producer warp =================
        if (lane == 0) {
            int phE[NSTAGE] = {0, 0};
#pragma unroll
            for (int l = 0; l < NSTAGE; l++) {   // prologue: fill both stages
                int k0, r0, c0;
                coords(bid, l, k0, r0, c0);
                uint32_t st = sb + (uint32_t)l * STAGE_BYTES;
                uint32_t bar = fullb + 8u * l;
                mbar_expect_tx(bar, STAGE_BYTES);
#pragma unroll
                for (int sub = 0; sub < 2; sub++) {
                    uint32_t ss2 = st + (uint32_t)sub * SUB_BYTES;
                    int kk = k0 + 64 * sub;
                    tma2d(&mA, ss2,          kk, r0, bar);
                    tma2d(&mQ, ss2 + 16384,  kk, c0, bar);
                    tma2d(&mK, ss2 + 24576,  kk, c0, bar);
                    tma2d(&mV, ss2 + 32768,  kk, c0, bar);
                }
            }
            for (int l = NSTAGE; l < L; l++) {
                const int s = l & 1;
                mbar_wait(emptyb + 8u * s, phE[s]);
                phE[s] ^= 1;
                int k0, r0, c0;
                coords(bid, l, k0, r0, c0);
                uint32_t st = sb + (uint32_t)s * STAGE_BYTES;
                uint32_t bar = fullb + 8u * s;
                mbar_expect_tx(bar, STAGE_BYTES);
#pragma unroll
                for (int sub = 0; sub < 2; sub++) {
                    uint32_t ss2 = st + (uint32_t)sub * SUB_BYTES;
                    int kk = k0 + 64 * sub;
                    tma2d(&mA, ss2,          kk, r0, bar);
                    tma2d(&mQ, ss2 + 16384,  kk, c0, bar);
                    tma2d(&mK, ss2 + 24576,  kk, c0, bar);
                    tma2d(&mV, ss2 + 32768,  kk, c0, bar);
                }
            }
        }
        return;
    }

    // ================= consumer warps (0..11) =================
    const int m  = wid >> 2;        // matrix: 0=Q, 1=K, 2=V
    const int wm = wid & 3;         // 32-row block within the 128-row tile

    const uint32_t sw   = lane & 7;
    const uint32_t chA  = lane >> 4;
    const uint32_t chB  = (lane >> 3) & 1;
    const uint32_t rowA = 32u * wm + (lane & 7) + 8u * ((lane >> 3) & 1);
    const uint32_t offA0 = rowA << 7;
    const uint32_t offA1 = (rowA + 16) << 7;
    const uint32_t rB   = (lane & 7) + 8u * (lane >> 4);
    const uint32_t stwOff = (uint32_t)(16384 + (m << 13));

    float acc[2][8][4];
#pragma unroll
    for (int mt = 0; mt < 2; mt++)
#pragma unroll
        for (int n = 0; n < 8; n++)
#pragma unroll
            for (int e = 0; e < 4; e++) acc[mt][n][e] = 0.f;

    int phF[NSTAGE] = {0, 0};

    for (int l = 0; l < L; l++) {
        const int s = l & 1;
        mbar_wait(fullb + 8u * s, phF[s]);
        phF[s] ^= 1;

        const uint32_t st = sb + (uint32_t)s * STAGE_BYTES;

        // fragment double-buffer across 8 K-steps (two 64-K subtiles)
        uint32_t a[2][2][4], b[2][4][4];
        {
            const uint32_t aoff = ((chA) ^ sw) << 4;
            const uint32_t boff = ((chB) ^ sw) << 4;
            ldm4(a[0][0], st + offA0 + aoff);
            ldm4(a[0][1], st + offA1 + aoff);
#pragma unroll
            for (int j = 0; j < 4; j++)
                ldm4(b[0][j], st + stwOff + ((16u * j + rB) << 7) + boff);
        }
#pragma unroll
        for (int i = 0; i < 8; i++) {
            const int cur = i & 1, nxt = cur ^ 1;
            if (i < 7) {
                const uint32_t sub = ((i + 1) >= 4) ? (uint32_t)SUB_BYTES : 0u;
                const uint32_t kk = (uint32_t)(2 * ((i + 1) & 3));
                const uint32_t aoff = ((kk + chA) ^ sw) << 4;
                const uint32_t boff = ((kk + chB) ^ sw) << 4;
                const uint32_t stn = st + sub;
                // interleave 6 LDSM (step i+1) among 16 HMMA (step i)
                ldm4(a[nxt][0], stn + offA0 + aoff);
                hmma(acc[0][0], a[cur][0], b[cur][0][0], b[cur][0][1]);
                hmma(acc[0][1], a[cur][0], b[cur][0][2], b[cur][0][3]);
                ldm4(a[nxt][1], stn + offA1 + aoff);
                hmma(acc[0][2], a[cur][0], b[cur][1][0], b[cur][1][1]);
                hmma(acc[0][3], a[cur][0], b[cur][1][2], b[cur][1][3]);
                ldm4(b[nxt][0], stn + stwOff + ((0u + rB) << 7) + boff);
                hmma(acc[0][4], a[cur][0], b[cur][2][0], b[cur][2][1]);
                hmma(acc[0][5], a[cur][0], b[cur][2][2], b[cur][2][3]);
                ldm4(b[nxt][1], stn + stwOff + ((16u + rB) << 7) + boff);
                hmma(acc[0][6], a[cur][0], b[cur][3][0], b[cur][3][1]);
                hmma(acc[0][7], a[cur][0], b[cur][3][2], b[cur][3][3]);
                ldm4(b[nxt][2], stn + stwOff + ((32u + rB) << 7) + boff);
                hmma(acc[1][0], a[cur][1], b[cur][0][0], b[cur][0][1]);
                hmma(acc[1][1], a[cur][1], b[cur][0][2], b[cur][0][3]);
                ldm4(b[nxt][3], stn + stwOff + ((48u + rB) << 7) + boff);
                hmma(acc[1][2], a[cur][1], b[cur][1][0], b[cur][1][1]);
                hmma(acc[1][3], a[cur][1], b[cur][1][2], b[cur][1][3]);
                hmma(acc[1][4], a[cur][1], b[cur][2][0], b[cur][2][1]);
                hmma(acc[1][5], a[cur][1], b[cur][2][2], b[cur][2][3]);
                hmma(acc[1][6], a[cur][1], b[cur][3][0], b[cur][3][1]);
                hmma(acc[1][7], a[cur][1], b[cur][3][2], b[cur][3][3]);
            } else {
#pragma unroll
                for (int mt = 0; mt < 2; mt++)
#pragma unroll
                    for (int j = 0; j < 4; j++) {
                        hmma(acc[mt][2 * j],     a[cur][mt], b[cur][j][0], b[cur][j][1]);
                        hmma(acc[mt][2 * j + 1], a[cur][mt], b[cur][j][2], b[cur][j][3]);
                    }
            }
        }

        // this warp done reading stage s
        if (lane == 0) mbar_arrive(emptyb + 8u * s);

        // ---- tile finished: specialized epilogue ----
        if ((l % CPT) == CPT - 1) {
            int t    = bid + GRID * (l / CPT);
            int rb   = t / NHEAD;
            int row0 = rb * 128;
            int col0 = (t - rb * NHEAD) * 64;
            const int g  = lane >> 2;
            const int tg = lane & 3;

            CONSUMER_BAR();   // BAR#1: V warps' reads of the PREVIOUS tile are done

            if (m < 2) {
                // Q,K warps: dump tiles to exchange buffers
                __half* bm = qbuf + m * (128 * BUF_STRIDE);
#pragma unroll
                for (int mt = 0; mt < 2; mt++) {
                    const int r0 = 32 * wm + 16 * mt + g;
#pragma unroll
                    for (int n = 0; n < 8; n++) {
                        const int cb = 8 * n + 2 * tg;
                        *(__half2*)(bm + (size_t)r0 * BUF_STRIDE + cb) =
                            __floats2half2_rn(acc[mt][n][0], acc[mt][n][1]);
                        *(__half2*)(bm + (size_t)(r0 + 8) * BUF_STRIDE + cb) =
                            __floats2half2_rn(acc[mt][n][2], acc[mt][n][3]);
                    }
                }
            }
            CONSUMER_BAR();   // BAR#2: q,k tiles visible

            if (m == 2) {
                // V warps: full attention epilogue (overlaps Q/K's next-tile GEMM)
                const float sc = 0.17677669529663687f;  // 1/sqrt(32)
#pragma unroll
                for (int mt = 0; mt < 2; mt++)
#pragma unroll
                    for (int rr = 0; rr < 2; rr++) {
                        const int row = 32 * wm + 16 * mt + 8 * rr + g;
                        const __half2* qr = (const __half2*)(qbuf + (size_t)row * BUF_STRIDE);
                        const __half2* kr = (const __half2*)(kbuf + (size_t)row * BUF_STRIDE);
                        float s00 = 0.f, s01 = 0.f, s10 = 0.f, s11 = 0.f;
#pragma unroll
                        for (int n = 0; n < 4; n++) {
                            int i = 4 * n + tg;          // half2 idx of cols 8n+2tg
                            float2 q0 = __half22float2(qr[i]);
                            float2 q1 = __half22float2(qr[16 + i]);
                            float2 k0 = __half22float2(kr[i]);
                            float2 k1 = __half22float2(kr[16 + i]);
                            s00 += q0.x * k0.x + q0.y * k0.y;
                            s01 += q0.x * k1.x + q0.y * k1.y;
                            s10 += q1.x * k0.x + q1.y * k0.y;
                            s11 += q1.x * k1.x + q1.y * k1.y;
                        }
                        s00 += __shfl_xor_sync(0xffffffffu, s00, 1);
                        s00 += __shfl_xor_sync(0xffffffffu, s00, 2);
                        s01 += __shfl_xor_sync(0xffffffffu, s01, 1);
                        s01 += __shfl_xor_sync(0xffffffffu, s01, 2);
                        s10 += __shfl_xor_sync(0xffffffffu, s10, 1);
                        s10 += __shfl_xor_sync(0xffffffffu, s10, 2);
                        s11 += __shfl_xor_sync(0xffffffffu, s11, 1);
                        s11 += __shfl_xor_sync(0xffffffffu, s11, 2);
                        s00 *= sc; s01 *= sc; s10 *= sc; s11 *= sc;
                        float m0 = fmaxf(s00, s01), m1 = fmaxf(s10, s11);
                        float e00 = __expf(s00 - m0), e01 = __expf(s01 - m0);
                        float e10 = __expf(s10 - m1), e11 = __expf(s11 - m1);
                        float r0i = 1.0f / (e00 + e01), r1i = 1.0f / (e10 + e11);
                        float a00 = e00 * r0i, a01 = e01 * r0i;
                        float a10 = e10 * r1i, a11 = e11 * r1i;

                        const float* xr = x + (size_t)(row0 + row) * DDIM + col0;
                        float* orow = out + (size_t)(row0 + row) * DDIM + col0;
#pragma unroll
                        for (int n = 0; n < 4; n++) {
                            const int c = 8 * n + 2 * tg;
                            float v0a = acc[mt][n][2 * rr],     v0b = acc[mt][n][2 * rr + 1];
                            float v1a = acc[mt][n + 4][2 * rr], v1b = acc[mt][n + 4][2 * rr + 1];
                            float2 x0 = *(const float2*)(xr + c);
                            float2 x1 = *(const float2*)(xr + 32 + c);
                            float2 o0, o1;
                            o0.x = a00 * v0a + a01 * v1a + x0.x;
                            o0.y = a00 * v0b + a01 * v1b + x0.y;
                            o1.x = a10 * v0a + a11 * v1a + x1.x;
                            o1.y = a10 * v0b + a11 * v1b + x1.y;
                            *(float2*)(orow + c)      = o0;
                            *(float2*)(orow + 32 + c) = o1;
                        }
                    }
            }

            // reset accumulators
#pragma unroll
            for (int mt = 0; mt < 2; mt++)
#pragma unroll
                for (int n = 0; n < 8; n++)
#pragma unroll
                    for (int e = 0; e < 4; e++) acc[mt][n][e] = 0.f;
        }
    }
}

// ================= launch =================
typedef CUresult (*PFN_encodeTiled)(CUtensorMap*, CUtensorMapDataType, cuuint32_t,
                                    void*, const cuuint64_t*, const cuuint64_t*,
                                    const cuuint32_t*, const cuuint32_t*,
                                    CUtensorMapInterleave, CUtensorMapSwizzle,
                                    CUtensorMapL2promotion, CUtensorMapFloatOOBfill);

extern "C" void kernel_launch(void* const* d_in, const int* in_sizes, int n_in,
                              void* d_out, int out_size) {
    const float* x     = (const float*)d_in[0];
    const float* Wq    = (const float*)d_in[1];
    const float* Wk    = (const float*)d_in[2];
    const float* Wv    = (const float*)d_in[3];
    const float* gamma = (const float*)d_in[4];
    const float* beta  = (const float*)d_in[5];
    float* out = (float*)d_out;

    PFN_encodeTiled enc = nullptr;
    cudaDriverEntryPointQueryResult qr;
    cudaGetDriverEntryPoint("cuTensorMapEncodeTiled", (void**)&enc,
                            cudaEnableDefault, &qr);

    void* xn_ptr = nullptr;
    void* w_ptr  = nullptr;
    cudaGetSymbolAddress(&xn_ptr, g_xn2);
    cudaGetSymbolAddress(&w_ptr,  g_w2);

    const cuuint32_t es[2] = {1, 1};
    CUtensorMap mA, mW[3];
    {
        cuuint64_t dims[2] = {DDIM, BS};
        cuuint64_t strd[1] = {DDIM * 2};
        cuuint32_t box[2]  = {64, 128};
        enc(&mA, CU_TENSOR_MAP_DATA_TYPE_FLOAT16, 2, xn_ptr, dims, strd, box, es,
            CU_TENSOR_MAP_INTERLEAVE_NONE, CU_TENSOR_MAP_SWIZZLE_128B,
            CU_TENSOR_MAP_L2_PROMOTION_L2_128B, CU_TENSOR_MAP_FLOAT_OOB_FILL_NONE);
    }
    for (int m = 0; m < 3; m++) {
        cuuint64_t dims[2] = {DDIM, DDIM};
        cuuint64_t strd[1] = {DDIM * 2};
        cuuint32_t box[2]  = {64, 64};
        void* base = (char*)w_ptr + (size_t)m * DDIM * DDIM * 2;
        enc(&mW[m], CU_TENSOR_MAP_DATA_TYPE_FLOAT16, 2, base, dims, strd, box, es,
            CU_TENSOR_MAP_INTERLEAVE_NONE, CU_TENSOR_MAP_SWIZZLE_128B,
            CU_TENSOR_MAP_L2_PROMOTION_L2_128B, CU_TENSOR_MAP_FLOAT_OOB_FILL_NONE);
    }

    cudaFuncSetAttribute(attn_kernel, cudaFuncAttributeMaxDynamicSharedMemorySize, SMEM_BYTES);

    prep_kernel<<<576 + BS / 8, 256>>>(x, Wq, Wk, Wv, gamma, beta);
    attn_kernel<<<GRID, NTHREADS, SMEM_BYTES>>>(x, out, mA, mW[0], mW[1], mW[2]);
}

// round 16
// speedup vs baseline: 1.2836x; 1.2836x over previous
#include <cuda_runtime.h>
#include <cuda.h>
#include <cuda_fp16.h>
#include <cstdint>

// ================= problem constants =================
#define BS      65536
#define DDIM    768
#define NHEAD   12
#define CPT     6                   // chunks per tile (768/128)
#define NTILES  6144                // (BS/128) * NHEAD
#define GRID    148
#define NTHREADS 416                // 12 consumer warps + 1 producer warp
#define SUB_BYTES 40960             // one 64-K subtile: A 16K + 3x8K W
#define STAGE_BYTES (2 * SUB_BYTES) // 81920 (128-K chunk)
#define NSTAGE  2
#define BUF_OFF (NSTAGE * STAGE_BYTES)           // 163840
#define BUF_STRIDE 72                            // halves per row (144B)
#define BUF_BYTES (128 * BUF_STRIDE * 2)         // 18432 per matrix
#define CTRL_OFF (BUF_OFF + 3 * BUF_BYTES)       // 219136
#define SMEM_BYTES (CTRL_OFF + 128)              // 219264

// ================= static device scratch (allowed) =================
__device__ __align__(128) __half g_xn2[(size_t)BS * DDIM];   // fp16 LN output
__device__ __align__(128) __half g_w2[3][DDIM * DDIM];       // fp16 Wq,Wk,Wv

// ================= helpers =================
__device__ __forceinline__ uint32_t smem_u32(const void* p) {
    uint32_t a;
    asm("{ .reg .u64 t; cvta.to.shared.u64 t, %1; cvt.u32.u64 %0, t; }" : "=r"(a) : "l"(p));
    return a;
}
__device__ __forceinline__ void ldm4(uint32_t* d, uint32_t addr) {
    asm volatile("ldmatrix.sync.aligned.m8n8.x4.shared.b16 {%0,%1,%2,%3}, [%4];"
                 : "=r"(d[0]), "=r"(d[1]), "=r"(d[2]), "=r"(d[3]) : "r"(addr));
}
__device__ __forceinline__ void hmma(float* c, const uint32_t* a, uint32_t b0, uint32_t b1) {
    asm volatile(
        "mma.sync.aligned.m16n8k16.row.col.f32.f16.f16.f32 "
        "{%0,%1,%2,%3},{%4,%5,%6,%7},{%8,%9},{%0,%1,%2,%3};"
        : "+f"(c[0]), "+f"(c[1]), "+f"(c[2]), "+f"(c[3])
        : "r"(a[0]), "r"(a[1]), "r"(a[2]), "r"(a[3]), "r"(b0), "r"(b1));
}
__device__ __forceinline__ void mbar_init(uint32_t addr, uint32_t cnt) {
    asm volatile("mbarrier.init.shared.b64 [%0], %1;" :: "r"(addr), "r"(cnt) : "memory");
}
__device__ __forceinline__ void mbar_arrive(uint32_t addr) {
    asm volatile("mbarrier.arrive.shared.b64 _, [%0];" :: "r"(addr) : "memory");
}
__device__ __forceinline__ void mbar_expect_tx(uint32_t addr, uint32_t bytes) {
    asm volatile("mbarrier.arrive.expect_tx.shared.b64 _, [%0], %1;"
                 :: "r"(addr), "r"(bytes) : "memory");
}
__device__ __forceinline__ void mbar_wait(uint32_t addr, uint32_t parity) {
    asm volatile(
        "{\n\t.reg .pred P;\n\t"
        "WAITLP_%=:\n\t"
        "mbarrier.try_wait.parity.acquire.cta.shared::cta.b64 P, [%0], %1, 0x989680;\n\t"
        "@!P bra WAITLP_%=;\n\t}"
        :: "r"(addr), "r"(parity) : "memory");
}
__device__ __forceinline__ void tma2d(const CUtensorMap* m, uint32_t dst,
                                      int cx, int cy, uint32_t bar) {
    asm volatile(
        "cp.async.bulk.tensor.2d.shared::cta.global.tile.mbarrier::complete_tx::bytes "
        "[%0], [%1, {%2, %3}], [%4];"
        :: "r"(dst), "l"(m), "r"(cx), "r"(cy), "r"(bar) : "memory");
}
#define FENCE_PROXY() asm volatile("fence.proxy.async.shared::cta;" ::: "memory")
#define CONSUMER_BAR() asm volatile("bar.sync 1, 384;" ::: "memory")

// ================= kernel 0: fused W->fp16 conversion + layernorm ==========
__global__ void __launch_bounds__(256) prep_kernel(const float* __restrict__ x,
                                                   const float* __restrict__ wq,
                                                   const float* __restrict__ wk,
                                                   const float* __restrict__ wv,
                                                   const float* __restrict__ gamma,
                                                   const float* __restrict__ beta) {
    if (blockIdx.x < 576) {
        int i = blockIdx.x * 256 + threadIdx.x;
        const float* srcs[3] = {wq, wk, wv};
#pragma unroll
        for (int m = 0; m < 3; m++) {
            float4 v = ((const float4*)srcs[m])[i];
            union { __half2 h[2]; uint2 u; } cvt;
            cvt.h[0] = __floats2half2_rn(v.x, v.y);
            cvt.h[1] = __floats2half2_rn(v.z, v.w);
            ((uint2*)g_w2[m])[i] = cvt.u;
        }
        return;
    }
    const int row  = (blockIdx.x - 576) * 8 + (threadIdx.x >> 5);
    const int lane = threadIdx.x & 31;
    const float4* xr = (const float4*)(x + (size_t)row * DDIM);
    float4 v[6];
    float s = 0.f;
#pragma unroll
    for (int i = 0; i < 6; i++) {
        v[i] = xr[lane + 32 * i];
        s += v[i].x + v[i].y + v[i].z + v[i].w;
    }
#pragma unroll
    for (int o = 16; o; o >>= 1) s += __shfl_xor_sync(0xffffffffu, s, o);
    const float mu = s * (1.0f / 768.0f);
    float ss = 0.f;
#pragma unroll
    for (int i = 0; i < 6; i++) {
        float a = v[i].x - mu, b = v[i].y - mu, c = v[i].z - mu, d = v[i].w - mu;
        ss += a * a + b * b + c * c + d * d;
    }
#pragma unroll
    for (int o = 16; o; o >>= 1) ss += __shfl_xor_sync(0xffffffffu, ss, o);
    const float inv = rsqrtf(ss * (1.0f / 768.0f) + 1e-6f);
    const float4* g4 = (const float4*)gamma;
    const float4* b4 = (const float4*)beta;
    uint2* dst = (uint2*)(g_xn2 + (size_t)row * DDIM);
#pragma unroll
    for (int i = 0; i < 6; i++) {
        float4 g = g4[lane + 32 * i];
        float4 bb = b4[lane + 32 * i];
        union { __half2 h[2]; uint2 u; } cvt;
        cvt.h[0] = __floats2half2_rn((v[i].x - mu) * inv * g.x + bb.x,
                                     (v[i].y - mu) * inv * g.y + bb.y);
        cvt.h[1] = __floats2half2_rn((v[i].z - mu) * inv * g.z + bb.z,
                                     (v[i].w - mu) * inv * g.w + bb.w);
        dst[lane + 32 * i] = cvt.u;
    }
}

// chunk index -> (k0, row0, col0); chunk covers 128 K-columns
__device__ __forceinline__ void coords(int bid, int l, int& k0, int& row0, int& col0) {
    int tl = l / CPT;
    int c  = l - tl * CPT;
    int t  = bid + GRID * tl;
    int rb = t / NHEAD;
    k0   = c * 128;
    row0 = rb * 128;
    col0 = (t - rb * NHEAD) * 64;
}

// ================= kernel 1: persistent fused QKV GEMM + attention =========
__global__ void __launch_bounds__(NTHREADS, 1) attn_kernel(
        const float* __restrict__ x, float* __restrict__ out,
        const __grid_constant__ CUtensorMap mA,
        const __grid_constant__ CUtensorMap mQ,
        const __grid_constant__ CUtensorMap mK,
        const __grid_constant__ CUtensorMap mV) {
    extern __shared__ __align__(1024) char smem[];
    const uint32_t sb = smem_u32(smem);
    const int tid  = threadIdx.x;
    const int wid  = tid >> 5;
    const int lane = tid & 31;
    const int bid  = blockIdx.x;

    const int ntiles = 41 + (bid < (NTILES - 41 * GRID) ? 1 : 0);  // 76 CTAs get 42
    const int L = ntiles * CPT;

    const uint32_t fullb  = sb + CTRL_OFF;        // 2 full barriers  @ +0,+8
    const uint32_t emptyb = sb + CTRL_OFF + 16;   // 2 empty barriers @ +16,+24
    const uint32_t epib   = sb + CTRL_OFF + 32;   // epilogue-release @ +32

    __half* qbuf = (__half*)(smem + BUF_OFF);
    __half* kbuf = qbuf + 128 * BUF_STRIDE;
    __half* vbuf = kbuf + 128 * BUF_STRIDE;

    if (tid == 0) {
#pragma unroll
        for (int s = 0; s < NSTAGE; s++) {
            mbar_init(fullb  + 8u * s, 1);
            mbar_init(emptyb + 8u * s, 12);
        }
        mbar_init(epib, 8);   // lane0 of warps 0..7 arrive after epilogue reads
        FENCE_PROXY();
    }
    __syncthreads();   // only CTA-wide barrier; roles split below

    if (wid == 12) {
        // ================= producer warp =================
        if (lane == 0) {
            int phE[NSTAGE] = {0, 0};
#pragma unroll
            for (int l = 0; l < NSTAGE; l++) {   // prologue: fill both stages
                int k0, r0, c0;
                coords(bid, l, k0, r0, c0);
                uint32_t st = sb + (uint32_t)l * STAGE_BYTES;
                uint32_t bar = fullb + 8u * l;
                mbar_expect_tx(bar, STAGE_BYTES);
#pragma unroll
                for (int sub = 0; sub < 2; sub++) {
                    uint32_t ss2 = st + (uint32_t)sub * SUB_BYTES;
                    int kk = k0 + 64 * sub;
                    tma2d(&mA, ss2,          kk, r0, bar);
                    tma2d(&mQ, ss2 + 16384,  kk, c0, bar);
                    tma2d(&mK, ss2 + 24576,  kk, c0, bar);
                    tma2d(&mV, ss2 + 32768,  kk, c0, bar);
                }
            }
            for (int l = NSTAGE; l < L; l++) {
                const int s = l & 1;
                mbar_wait(emptyb + 8u * s, phE[s]);
                phE[s] ^= 1;
                int k0, r0, c0;
                coords(bid, l, k0, r0, c0);
                uint32_t st = sb + (uint32_t)s * STAGE_BYTES;
                uint32_t bar = fullb + 8u * s;
                mbar_expect_tx(bar, STAGE_BYTES);
#pragma unroll
                for (int sub = 0; sub < 2; sub++) {
                    uint32_t ss2 = st + (uint32_t)sub * SUB_BYTES;
                    int kk = k0 + 64 * sub;
                    tma2d(&mA, ss2,          kk, r0, bar);
                    tma2d(&mQ, ss2 + 16384,  kk, c0, bar);
                    tma2d(&mK, ss2 + 24576,  kk, c0, bar);
                    tma2d(&mV, ss2 + 32768,  kk, c0, bar);
                }
            }
        }
        return;
    }

    // ================= consumer warps (0..11) =================
    const int m  = wid >> 2;        // matrix: 0=Q, 1=K, 2=V
    const int wm = wid & 3;         // 32-row block within the 128-row tile

    const uint32_t sw   = lane & 7;
    const uint32_t chA  = lane >> 4;
    const uint32_t chB  = (lane >> 3) & 1;
    const uint32_t rowA = 32u * wm + (lane & 7) + 8u * ((lane >> 3) & 1);
    const uint32_t offA0 = rowA << 7;
    const uint32_t offA1 = (rowA + 16) << 7;
    const uint32_t rB   = (lane & 7) + 8u * (lane >> 4);
    const uint32_t stwOff = (uint32_t)(16384 + (m << 13));

    float acc[2][8][4];
#pragma unroll
    for (int mt = 0; mt < 2; mt++)
#pragma unroll
        for (int n = 0; n < 8; n++)
#pragma unroll
            for (int e = 0; e < 4; e++) acc[mt][n][e] = 0.f;

    int phF[NSTAGE] = {0, 0};
    int phEpi = 0;

    for (int l = 0; l < L; l++) {
        const int s = l & 1;
        mbar_wait(fullb + 8u * s, phF[s]);
        phF[s] ^= 1;

        const uint32_t st = sb + (uint32_t)s * STAGE_BYTES;

        // fragment double-buffer across 8 K-steps (two 64-K subtiles)
        uint32_t a[2][2][4], b[2][4][4];
        {
            const uint32_t aoff = ((chA) ^ sw) << 4;
            const uint32_t boff = ((chB) ^ sw) << 4;
            ldm4(a[0][0], st + offA0 + aoff);
            ldm4(a[0][1], st + offA1 + aoff);
#pragma unroll
            for (int j = 0; j < 4; j++)
                ldm4(b[0][j], st + stwOff + ((16u * j + rB) << 7) + boff);
        }
#pragma unroll
        for (int i = 0; i < 8; i++) {
            const int cur = i & 1, nxt = cur ^ 1;
            if (i < 7) {
                const uint32_t sub = ((i + 1) >= 4) ? (uint32_t)SUB_BYTES : 0u;
                const uint32_t kk = (uint32_t)(2 * ((i + 1) & 3));
                const uint32_t aoff = ((kk + chA) ^ sw) << 4;
                const uint32_t boff = ((kk + chB) ^ sw) << 4;
                const uint32_t stn = st + sub;
                // interleave 6 LDSM (step i+1) among 16 HMMA (step i)
                ldm4(a[nxt][0], stn + offA0 + aoff);
                hmma(acc[0][0], a[cur][0], b[cur][0][0], b[cur][0][1]);
                hmma(acc[0][1], a[cur][0], b[cur][0][2], b[cur][0][3]);
                ldm4(a[nxt][1], stn + offA1 + aoff);
                hmma(acc[0][2], a[cur][0], b[cur][1][0], b[cur][1][1]);
                hmma(acc[0][3], a[cur][0], b[cur][1][2], b[cur][1][3]);
                ldm4(b[nxt][0], stn + stwOff + ((0u + rB) << 7) + boff);
                hmma(acc[0][4], a[cur][0], b[cur][2][0], b[cur][2][1]);
                hmma(acc[0][5], a[cur][0], b[cur][2][2], b[cur][2][3]);
                ldm4(b[nxt][1], stn + stwOff + ((16u + rB) << 7) + boff);
                hmma(acc[0][6], a[cur][0], b[cur][3][0], b[cur][3][1]);
                hmma(acc[0][7], a[cur][0], b[cur][3][2], b[cur][3][3]);
                ldm4(b[nxt][2], stn + stwOff + ((32u + rB) << 7) + boff);
                hmma(acc[1][0], a[cur][1], b[cur][0][0], b[cur][0][1]);
                hmma(acc[1][1], a[cur][1], b[cur][0][2], b[cur][0][3]);
                ldm4(b[nxt][3], stn + stwOff + ((48u + rB) << 7) + boff);
                hmma(acc[1][2], a[cur][1], b[cur][1][0], b[cur][1][1]);
                hmma(acc[1][3], a[cur][1], b[cur][1][2], b[cur][1][3]);
                hmma(acc[1][4], a[cur][1], b[cur][2][0], b[cur][2][1]);
                hmma(acc[1][5], a[cur][1], b[cur][2][2], b[cur][2][3]);
                hmma(acc[1][6], a[cur][1], b[cur][3][0], b[cur][3][1]);
                hmma(acc[1][7], a[cur][1], b[cur][3][2], b[cur][3][3]);
            } else {
#pragma unroll
                for (int mt = 0; mt < 2; mt++)
#pragma unroll
                    for (int j = 0; j < 4; j++) {
                        hmma(acc[mt][2 * j],     a[cur][mt], b[cur][j][0], b[cur][j][1]);
                        hmma(acc[mt][2 * j + 1], a[cur][mt], b[cur][j][2], b[cur][j][3]);
                    }
            }
        }

        // this warp done reading stage s
        if (lane == 0) mbar_arrive(emptyb + 8u * s);

        // ---- tile finished: epilogue via fp16 smem buffers ----
        if ((l % CPT) == CPT - 1) {
            int t    = bid + GRID * (l / CPT);
            int rb   = t / NHEAD;
            int row0 = rb * 128;
            int col0 = (t - rb * NHEAD) * 64;

            // deferred release: previous tile's attention readers must be done
            if (l > CPT) {
                mbar_wait(epib, phEpi);
                phEpi ^= 1;
            }

            __half* bm = qbuf + m * (128 * BUF_STRIDE);
            const int g  = lane >> 2;
            const int tg = lane & 3;
#pragma unroll
            for (int mt = 0; mt < 2; mt++) {
                const int r0 = 32 * wm + 16 * mt + g;
#pragma unroll
                for (int n = 0; n < 8; n++) {
                    const int cb = 8 * n + 2 * tg;
                    *(__half2*)(bm + (size_t)r0 * BUF_STRIDE + cb) =
                        __floats2half2_rn(acc[mt][n][0], acc[mt][n][1]);
                    *(__half2*)(bm + (size_t)(r0 + 8) * BUF_STRIDE + cb) =
                        __floats2half2_rn(acc[mt][n][2], acc[mt][n][3]);
                }
            }
            CONSUMER_BAR();   // all dumps visible

            // 256 threads: per-(row,p) 2x2 attention + residual.
            // warps 8..11 (tid >= 256) skip straight into the next tile's GEMM.
            if (tid < 256) {
                const int row = tid >> 1;
                const int p   = tid & 1;
                const __half2* qb2 = (const __half2*)(qbuf + (size_t)row * BUF_STRIDE + 32 * p);
                const __half2* kb2 = (const __half2*)(kbuf + (size_t)row * BUF_STRIDE);
                const __half2* vb2 = (const __half2*)(vbuf + (size_t)row * BUF_STRIDE);
                float s0 = 0.f, s1 = 0.f;
#pragma unroll
                for (int i = 0; i < 16; i++) {
                    float2 q  = __half22float2(qb2[i]);
                    float2 k0 = __half22float2(kb2[i]);
                    float2 k1 = __half22float2(kb2[16 + i]);
                    s0 += q.x * k0.x + q.y * k0.y;
                    s1 += q.x * k1.x + q.y * k1.y;
                }
                const float sc = 0.17677669529663687f;  // 1/sqrt(32)
                s0 *= sc; s1 *= sc;
                float mx = fmaxf(s0, s1);
                float e0 = __expf(s0 - mx), e1 = __expf(s1 - mx);
                float rs = 1.0f / (e0 + e1);
                float a0 = e0 * rs, a1 = e1 * rs;

                const size_t base = (size_t)(row0 + row) * DDIM + col0 + 32 * p;
                const float4* xi = (const float4*)(x + base);
                float4* op = (float4*)(out + base);
#pragma unroll
                for (int i = 0; i < 8; i++) {
                    float4 xv = xi[i];
                    float2 va = __half22float2(vb2[2 * i]);
                    float2 vb = __half22float2(vb2[2 * i + 1]);
                    float2 wa = __half22float2(vb2[16 + 2 * i]);
                    float2 wb = __half22float2(vb2[16 + 2 * i + 1]);
                    float4 o;
                    o.x = a0 * va.x + a1 * wa.x + xv.x;
                    o.y = a0 * va.y + a1 * wa.y + xv.y;
                    o.z = a0 * vb.x + a1 * wb.x + xv.z;
                    o.w = a0 * vb.y + a1 * wb.y + xv.w;
                    op[i] = o;
                }
                if (lane == 0) mbar_arrive(epib);   // buffers released
            }

            // reset accumulators
#pragma unroll
            for (int mt = 0; mt < 2; mt++)
#pragma unroll
                for (int n = 0; n < 8; n++)
#pragma unroll
                    for (int e = 0; e < 4; e++) acc[mt][n][e] = 0.f;
        }
    }
}

// ================= launch =================
typedef CUresult (*PFN_encodeTiled)(CUtensorMap*, CUtensorMapDataType, cuuint32_t,
                                    void*, const cuuint64_t*, const cuuint64_t*,
                                    const cuuint32_t*, const cuuint32_t*,
                                    CUtensorMapInterleave, CUtensorMapSwizzle,
                                    CUtensorMapL2promotion, CUtensorMapFloatOOBfill);

extern "C" void kernel_launch(void* const* d_in, const int* in_sizes, int n_in,
                              void* d_out, int out_size) {
    const float* x     = (const float*)d_in[0];
    const float* Wq    = (const float*)d_in[1];
    const float* Wk    = (const float*)d_in[2];
    const float* Wv    = (const float*)d_in[3];
    const float* gamma = (const float*)d_in[4];
    const float* beta  = (const float*)d_in[5];
    float* out = (float*)d_out;

    PFN_encodeTiled enc = nullptr;
    cudaDriverEntryPointQueryResult qr;
    cudaGetDriverEntryPoint("cuTensorMapEncodeTiled", (void**)&enc,
                            cudaEnableDefault, &qr);

    void* xn_ptr = nullptr;
    void* w_ptr  = nullptr;
    cudaGetSymbolAddress(&xn_ptr, g_xn2);
    cudaGetSymbolAddress(&w_ptr,  g_w2);

    const cuuint32_t es[2] = {1, 1};
    CUtensorMap mA, mW[3];
    {
        cuuint64_t dims[2] = {DDIM, BS};
        cuuint64_t strd[1] = {DDIM * 2};
        cuuint32_t box[2]  = {64, 128};
        enc(&mA, CU_TENSOR_MAP_DATA_TYPE_FLOAT16, 2, xn_ptr, dims, strd, box, es,
            CU_TENSOR_MAP_INTERLEAVE_NONE, CU_TENSOR_MAP_SWIZZLE_128B,
            CU_TENSOR_MAP_L2_PROMOTION_L2_128B, CU_TENSOR_MAP_FLOAT_OOB_FILL_NONE);
    }
    for (int m = 0; m < 3; m++) {
        cuuint64_t dims[2] = {DDIM, DDIM};
        cuuint64_t strd[1] = {DDIM * 2};
        cuuint32_t box[2]  = {64, 64};
        void* base = (char*)w_ptr + (size_t)m * DDIM * DDIM * 2;
        enc(&mW[m], CU_TENSOR_MAP_DATA_TYPE_FLOAT16, 2, base, dims, strd, box, es,
            CU_TENSOR_MAP_INTERLEAVE_NONE, CU_TENSOR_MAP_SWIZZLE_128B,
            CU_TENSOR_MAP_L2_PROMOTION_L2_128B, CU_TENSOR_MAP_FLOAT_OOB_FILL_NONE);
    }

    cudaFuncSetAttribute(attn_kernel, cudaFuncAttributeMaxDynamicSharedMemorySize, SMEM_BYTES);

    prep_kernel<<<576 + BS / 8, 256>>>(x, Wq, Wk, Wv, gamma, beta);
    attn_kernel<<<GRID, NTHREADS, SMEM_BYTES>>>(x, out, mA, mW[0], mW[1], mW[2]);
}

// round 17
// speedup vs baseline: 1.3292x; 1.0355x over previous
#include <cuda_runtime.h>
#include <cuda.h>
#include <cuda_fp16.h>
#include <cstdint>

// ================= problem constants =================
#define BS      65536
#define DDIM    768
#define NHEAD   12
#define CPT     6                   // chunks per tile (768/128)
#define NTILES  6144                // (BS/128) * NHEAD
#define GRID    148
#define NTHREADS 416                // 12 consumer warps + 1 producer warp
#define SUB_BYTES 40960             // one 64-K subtile: A 16K + 3x8K W
#define STAGE_BYTES (2 * SUB_BYTES) // 81920 (128-K chunk)
#define NSTAGE  2
#define BUF_OFF (NSTAGE * STAGE_BYTES)           // 163840
#define BUF_STRIDE 72                            // halves per row (144B)
#define BUF_BYTES (128 * BUF_STRIDE * 2)         // 18432 per matrix
#define CTRL_OFF (BUF_OFF + 3 * BUF_BYTES)       // 219136
#define SMEM_BYTES (CTRL_OFF + 128)              // 219264

// ================= static device scratch (allowed) =================
__device__ __align__(128) __half g_xn2[(size_t)BS * DDIM];   // fp16 LN output
__device__ __align__(128) __half g_w2[3][DDIM * DDIM];       // fp16 Wq,Wk,Wv

// ================= helpers =================
__device__ __forceinline__ uint32_t smem_u32(const void* p) {
    uint32_t a;
    asm("{ .reg .u64 t; cvta.to.shared.u64 t, %1; cvt.u32.u64 %0, t; }" : "=r"(a) : "l"(p));
    return a;
}
__device__ __forceinline__ void ldm4(uint32_t* d, uint32_t addr) {
    asm volatile("ldmatrix.sync.aligned.m8n8.x4.shared.b16 {%0,%1,%2,%3}, [%4];"
                 : "=r"(d[0]), "=r"(d[1]), "=r"(d[2]), "=r"(d[3]) : "r"(addr));
}
__device__ __forceinline__ void hmma(float* c, const uint32_t* a, uint32_t b0, uint32_t b1) {
    asm volatile(
        "mma.sync.aligned.m16n8k16.row.col.f32.f16.f16.f32 "
        "{%0,%1,%2,%3},{%4,%5,%6,%7},{%8,%9},{%0,%1,%2,%3};"
        : "+f"(c[0]), "+f"(c[1]), "+f"(c[2]), "+f"(c[3])
        : "r"(a[0]), "r"(a[1]), "r"(a[2]), "r"(a[3]), "r"(b0), "r"(b1));
}
__device__ __forceinline__ void mbar_init(uint32_t addr, uint32_t cnt) {
    asm volatile("mbarrier.init.shared.b64 [%0], %1;" :: "r"(addr), "r"(cnt) : "memory");
}
__device__ __forceinline__ void mbar_arrive(uint32_t addr) {
    asm volatile("mbarrier.arrive.shared.b64 _, [%0];" :: "r"(addr) : "memory");
}
__device__ __forceinline__ void mbar_expect_tx(uint32_t addr, uint32_t bytes) {
    asm volatile("mbarrier.arrive.expect_tx.shared.b64 _, [%0], %1;"
                 :: "r"(addr), "r"(bytes) : "memory");
}
__device__ __forceinline__ void mbar_wait(uint32_t addr, uint32_t parity) {
    asm volatile(
        "{\n\t.reg .pred P;\n\t"
        "WAITLP_%=:\n\t"
        "mbarrier.try_wait.parity.acquire.cta.shared::cta.b64 P, [%0], %1, 0x989680;\n\t"
        "@!P bra WAITLP_%=;\n\t}"
        :: "r"(addr), "r"(parity) : "memory");
}
__device__ __forceinline__ void tma2d(const CUtensorMap* m, uint32_t dst,
                                      int cx, int cy, uint32_t bar) {
    asm volatile(
        "cp.async.bulk.tensor.2d.shared::cta.global.tile.mbarrier::complete_tx::bytes "
        "[%0], [%1, {%2, %3}], [%4];"
        :: "r"(dst), "l"(m), "r"(cx), "r"(cy), "r"(bar) : "memory");
}
#define FENCE_PROXY() asm volatile("fence.proxy.async.shared::cta;" ::: "memory")
#define CONSUMER_BAR() asm volatile("bar.sync 1, 384;" ::: "memory")

// ================= kernel 0: fused W->fp16 conversion + layernorm ==========
__global__ void __launch_bounds__(256) prep_kernel(const float* __restrict__ x,
                                                   const float* __restrict__ wq,
                                                   const float* __restrict__ wk,
                                                   const float* __restrict__ wv,
                                                   const float* __restrict__ gamma,
                                                   const float* __restrict__ beta) {
    if (blockIdx.x < 576) {
        int i = blockIdx.x * 256 + threadIdx.x;
        const float* srcs[3] = {wq, wk, wv};
#pragma unroll
        for (int m = 0; m < 3; m++) {
            float4 v = ((const float4*)srcs[m])[i];
            union { __half2 h[2]; uint2 u; } cvt;
            cvt.h[0] = __floats2half2_rn(v.x, v.y);
            cvt.h[1] = __floats2half2_rn(v.z, v.w);
            ((uint2*)g_w2[m])[i] = cvt.u;
        }
        return;
    }
    const int row  = (blockIdx.x - 576) * 8 + (threadIdx.x >> 5);
    const int lane = threadIdx.x & 31;
    const float4* xr = (const float4*)(x + (size_t)row * DDIM);
    float4 v[6];
    float s = 0.f;
#pragma unroll
    for (int i = 0; i < 6; i++) {
        v[i] = xr[lane + 32 * i];
        s += v[i].x + v[i].y + v[i].z + v[i].w;
    }
#pragma unroll
    for (int o = 16; o; o >>= 1) s += __shfl_xor_sync(0xffffffffu, s, o);
    const float mu = s * (1.0f / 768.0f);
    float ss = 0.f;
#pragma unroll
    for (int i = 0; i < 6; i++) {
        float a = v[i].x - mu, b = v[i].y - mu, c = v[i].z - mu, d = v[i].w - mu;
        ss += a * a + b * b + c * c + d * d;
    }
#pragma unroll
    for (int o = 16; o; o >>= 1) ss += __shfl_xor_sync(0xffffffffu, ss, o);
    const float inv = rsqrtf(ss * (1.0f / 768.0f) + 1e-6f);
    const float4* g4 = (const float4*)gamma;
    const float4* b4 = (const float4*)beta;
    uint2* dst = (uint2*)(g_xn2 + (size_t)row * DDIM);
#pragma unroll
    for (int i = 0; i < 6; i++) {
        float4 g = g4[lane + 32 * i];
        float4 bb = b4[lane + 32 * i];
        union { __half2 h[2]; uint2 u; } cvt;
        cvt.h[0] = __floats2half2_rn((v[i].x - mu) * inv * g.x + bb.x,
                                     (v[i].y - mu) * inv * g.y + bb.y);
        cvt.h[1] = __floats2half2_rn((v[i].z - mu) * inv * g.z + bb.z,
                                     (v[i].w - mu) * inv * g.w + bb.w);
        dst[lane + 32 * i] = cvt.u;
    }
}

// chunk index -> (k0, row0, col0); chunk covers 128 K-columns
__device__ __forceinline__ void coords(int bid, int l, int& k0, int& row0, int& col0) {
    int tl = l / CPT;
    int c  = l - tl * CPT;
    int t  = bid + GRID * tl;
    int rb = t / NHEAD;
    k0   = c * 128;
    row0 = rb * 128;
    col0 = (t - rb * NHEAD) * 64;
}

// 256-thread 2x2 attention for one finished tile (reads fp16 exchange bufs)
__device__ __forceinline__ void do_attention(const float* __restrict__ x,
                                             float* __restrict__ out,
                                             const __half* qbuf, const __half* kbuf,
                                             const __half* vbuf,
                                             int row0, int col0, int tid,
                                             uint32_t epib, bool arrive) {
    if (tid < 256) {
        const int row = tid >> 1;
        const int p   = tid & 1;
        const size_t base = (size_t)(row0 + row) * DDIM + col0 + 32 * p;
        const float4* xi = (const float4*)(x + base);
        // prefetch residual input first: LDG latency hides under score compute
        float4 xv[8];
#pragma unroll
        for (int i = 0; i < 8; i++) xv[i] = xi[i];

        const __half2* qb2 = (const __half2*)(qbuf + (size_t)row * BUF_STRIDE + 32 * p);
        const __half2* kb2 = (const __half2*)(kbuf + (size_t)row * BUF_STRIDE);
        const __half2* vb2 = (const __half2*)(vbuf + (size_t)row * BUF_STRIDE);
        float s0 = 0.f, s1 = 0.f;
#pragma unroll
        for (int i = 0; i < 16; i++) {
            float2 q  = __half22float2(qb2[i]);
            float2 k0 = __half22float2(kb2[i]);
            float2 k1 = __half22float2(kb2[16 + i]);
            s0 += q.x * k0.x + q.y * k0.y;
            s1 += q.x * k1.x + q.y * k1.y;
        }
        const float sc = 0.17677669529663687f;  // 1/sqrt(32)
        s0 *= sc; s1 *= sc;
        float mx = fmaxf(s0, s1);
        float e0 = __expf(s0 - mx), e1 = __expf(s1 - mx);
        float rs = 1.0f / (e0 + e1);
        float a0 = e0 * rs, a1 = e1 * rs;

        float4* op = (float4*)(out + base);
#pragma unroll
        for (int i = 0; i < 8; i++) {
            float2 va = __half22float2(vb2[2 * i]);
            float2 vb = __half22float2(vb2[2 * i + 1]);
            float2 wa = __half22float2(vb2[16 + 2 * i]);
            float2 wb = __half22float2(vb2[16 + 2 * i + 1]);
            float4 o;
            o.x = a0 * va.x + a1 * wa.x + xv[i].x;
            o.y = a0 * va.y + a1 * wa.y + xv[i].y;
            o.z = a0 * vb.x + a1 * wb.x + xv[i].z;
            o.w = a0 * vb.y + a1 * wb.y + xv[i].w;
            op[i] = o;
        }
        if (arrive && (tid & 31) == 0) mbar_arrive(epib);   // buffers released
    }
}

// ================= kernel 1: persistent fused QKV GEMM + attention =========
__global__ void __launch_bounds__(NTHREADS, 1) attn_kernel(
        const float* __restrict__ x, float* __restrict__ out,
        const __grid_constant__ CUtensorMap mA,
        const __grid_constant__ CUtensorMap mQ,
        const __grid_constant__ CUtensorMap mK,
        const __grid_constant__ CUtensorMap mV) {
    extern __shared__ __align__(1024) char smem[];
    const uint32_t sb = smem_u32(smem);
    const int tid  = threadIdx.x;
    const int wid  = tid >> 5;
    const int lane = tid & 31;
    const int bid  = blockIdx.x;

    const int ntiles = 41 + (bid < (NTILES - 41 * GRID) ? 1 : 0);  // 76 CTAs get 42
    const int L = ntiles * CPT;

    const uint32_t fullb  = sb + CTRL_OFF;        // 2 full barriers  @ +0,+8
    const uint32_t emptyb = sb + CTRL_OFF + 16;   // 2 empty barriers @ +16,+24
    const uint32_t epib   = sb + CTRL_OFF + 32;   // epilogue-release @ +32

    __half* qbuf = (__half*)(smem + BUF_OFF);
    __half* kbuf = qbuf + 128 * BUF_STRIDE;
    __half* vbuf = kbuf + 128 * BUF_STRIDE;

    if (tid == 0) {
#pragma unroll
        for (int s = 0; s < NSTAGE; s++) {
            mbar_init(fullb  + 8u * s, 1);
            mbar_init(emptyb + 8u * s, 12);
        }
        mbar_init(epib, 8);   // lane0 of warps 0..7 arrive after epilogue reads
        FENCE_PROXY();
    }
    __syncthreads();   // only CTA-wide barrier; roles split below

    if (wid == 12) {
        // ================= producer warp =================
        if (lane == 0) {
            int phE[NSTAGE] = {0, 0};
#pragma unroll
            for (int l = 0; l < NSTAGE; l++) {   // prologue: fill both stages
                int k0, r0, c0;
                coords(bid, l, k0, r0, c0);
                uint32_t st = sb + (uint32_t)l * STAGE_BYTES;
                uint32_t bar = fullb + 8u * l;
                mbar_expect_tx(bar, STAGE_BYTES);
#pragma unroll
                for (int sub = 0; sub < 2; sub++) {
                    uint32_t ss2 = st + (uint32_t)sub * SUB_BYTES;
                    int kk = k0 + 64 * sub;
                    tma2d(&mA, ss2,          kk, r0, bar);
                    tma2d(&mQ, ss2 + 16384,  kk, c0, bar);
                    tma2d(&mK, ss2 + 24576,  kk, c0, bar);
                    tma2d(&mV, ss2 + 32768,  kk, c0, bar);
                }
            }
            for (int l = NSTAGE; l < L; l++) {
                const int s = l & 1;
                mbar_wait(emptyb + 8u * s, phE[s]);
                phE[s] ^= 1;
                int k0, r0, c0;
                coords(bid, l, k0, r0, c0);
                uint32_t st = sb + (uint32_t)s * STAGE_BYTES;
                uint32_t bar = fullb + 8u * s;
                mbar_expect_tx(bar, STAGE_BYTES);
#pragma unroll
                for (int sub = 0; sub < 2; sub++) {
                    uint32_t ss2 = st + (uint32_t)sub * SUB_BYTES;
                    int kk = k0 + 64 * sub;
                    tma2d(&mA, ss2,          kk, r0, bar);
                    tma2d(&mQ, ss2 + 16384,  kk, c0, bar);
                    tma2d(&mK, ss2 + 24576,  kk, c0, bar);
                    tma2d(&mV, ss2 + 32768,  kk, c0, bar);
                }
            }
        }
        return;
    }

    // ================= consumer warps (0..11) =================
    const int m  = wid >> 2;        // matrix: 0=Q, 1=K, 2=V
    const int wm = wid & 3;         // 32-row block within the 128-row tile

    const uint32_t sw   = lane & 7;
    const uint32_t chA  = lane >> 4;
    const uint32_t chB  = (lane >> 3) & 1;
    const uint32_t rowA = 32u * wm + (lane & 7) + 8u * ((lane >> 3) & 1);
    const uint32_t offA0 = rowA << 7;
    const uint32_t offA1 = (rowA + 16) << 7;
    const uint32_t rB   = (lane & 7) + 8u * (lane >> 4);
    const uint32_t stwOff = (uint32_t)(16384 + (m << 13));

    float acc[2][8][4];
#pragma unroll
    for (int mt = 0; mt < 2; mt++)
#pragma unroll
        for (int n = 0; n < 8; n++)
#pragma unroll
            for (int e = 0; e < 4; e++) acc[mt][n][e] = 0.f;

    int phF[NSTAGE] = {0, 0};
    int phEpi = 0;

    for (int l = 0; l < L; l++) {
        const int s = l & 1;
        mbar_wait(fullb + 8u * s, phF[s]);
        phF[s] ^= 1;

        const uint32_t st = sb + (uint32_t)s * STAGE_BYTES;

        // fragment double-buffer across 8 K-steps (two 64-K subtiles)
        uint32_t a[2][2][4], b[2][4][4];
        {
            const uint32_t aoff = ((chA) ^ sw) << 4;
            const uint32_t boff = ((chB) ^ sw) << 4;
            ldm4(a[0][0], st + offA0 + aoff);
            ldm4(a[0][1], st + offA1 + aoff);
#pragma unroll
            for (int j = 0; j < 4; j++)
                ldm4(b[0][j], st + stwOff + ((16u * j + rB) << 7) + boff);
        }
#pragma unroll
        for (int i = 0; i < 8; i++) {
            const int cur = i & 1, nxt = cur ^ 1;
            if (i < 7) {
                const uint32_t sub = ((i + 1) >= 4) ? (uint32_t)SUB_BYTES : 0u;
                const uint32_t kk = (uint32_t)(2 * ((i + 1) & 3));
                const uint32_t aoff = ((kk + chA) ^ sw) << 4;
                const uint32_t boff = ((kk + chB) ^ sw) << 4;
                const uint32_t stn = st + sub;
                // interleave 6 LDSM (step i+1) among 16 HMMA (step i)
                ldm4(a[nxt][0], stn + offA0 + aoff);
                hmma(acc[0][0], a[cur][0], b[cur][0][0], b[cur][0][1]);
                hmma(acc[0][1], a[cur][0], b[cur][0][2], b[cur][0][3]);
                ldm4(a[nxt][1], stn + offA1 + aoff);
                hmma(acc[0][2], a[cur][0], b[cur][1][0], b[cur][1][1]);
                hmma(acc[0][3], a[cur][0], b[cur][1][2], b[cur][1][3]);
                ldm4(b[nxt][0], stn + stwOff + ((0u + rB) << 7) + boff);
                hmma(acc[0][4], a[cur][0], b[cur][2][0], b[cur][2][1]);
                hmma(acc[0][5], a[cur][0], b[cur][2][2], b[cur][2][3]);
                ldm4(b[nxt][1], stn + stwOff + ((16u + rB) << 7) + boff);
                hmma(acc[0][6], a[cur][0], b[cur][3][0], b[cur][3][1]);
                hmma(acc[0][7], a[cur][0], b[cur][3][2], b[cur][3][3]);
                ldm4(b[nxt][2], stn + stwOff + ((32u + rB) << 7) + boff);
                hmma(acc[1][0], a[cur][1], b[cur][0][0], b[cur][0][1]);
                hmma(acc[1][1], a[cur][1], b[cur][0][2], b[cur][0][3]);
                ldm4(b[nxt][3], stn + stwOff + ((48u + rB) << 7) + boff);
                hmma(acc[1][2], a[cur][1], b[cur][1][0], b[cur][1][1]);
                hmma(acc[1][3], a[cur][1], b[cur][1][2], b[cur][1][3]);
                hmma(acc[1][4], a[cur][1], b[cur][2][0], b[cur][2][1]);
                hmma(acc[1][5], a[cur][1], b[cur][2][2], b[cur][2][3]);
                hmma(acc[1][6], a[cur][1], b[cur][3][0], b[cur][3][1]);
                hmma(acc[1][7], a[cur][1], b[cur][3][2], b[cur][3][3]);
            } else {
#pragma unroll
                for (int mt = 0; mt < 2; mt++)
#pragma unroll
                    for (int j = 0; j < 4; j++) {
                        hmma(acc[mt][2 * j],     a[cur][mt], b[cur][j][0], b[cur][j][1]);
                        hmma(acc[mt][2 * j + 1], a[cur][mt], b[cur][j][2], b[cur][j][3]);
                    }
            }
        }

        // this warp done reading stage s
        if (lane == 0) mbar_arrive(emptyb + 8u * s);

        // ---- deferred attention: previous tile, one chunk into this tile ----
        if ((l % CPT) == 0 && l > 0) {
            int tp   = bid + GRID * (l / CPT - 1);
            int rbp  = tp / NHEAD;
            do_attention(x, out, qbuf, kbuf, vbuf,
                         rbp * 128, (tp - rbp * NHEAD) * 64, tid, epib, true);
        }

        // ---- tile finished: dump accumulators to exchange buffers ----
        if ((l % CPT) == CPT - 1) {
            // deferred release: previous tile's attention readers must be done
            if (l > CPT) {
                mbar_wait(epib, phEpi);
                phEpi ^= 1;
            }

            __half* bm = qbuf + m * (128 * BUF_STRIDE);
            const int g  = lane >> 2;
            const int tg = lane & 3;
#pragma unroll
            for (int mt = 0; mt < 2; mt++) {
                const int r0 = 32 * wm + 16 * mt + g;
#pragma unroll
                for (int n = 0; n < 8; n++) {
                    const int cb = 8 * n + 2 * tg;
                    *(__half2*)(bm + (size_t)r0 * BUF_STRIDE + cb) =
                        __floats2half2_rn(acc[mt][n][0], acc[mt][n][1]);
                    *(__half2*)(bm + (size_t)(r0 + 8) * BUF_STRIDE + cb) =
                        __floats2half2_rn(acc[mt][n][2], acc[mt][n][3]);
                }
            }
            CONSUMER_BAR();   // all dumps visible

            // reset accumulators
#pragma unroll
            for (int mt = 0; mt < 2; mt++)
#pragma unroll
                for (int n = 0; n < 8; n++)
#pragma unroll
                    for (int e = 0; e < 4; e++) acc[mt][n][e] = 0.f;
        }
    }

    // ---- final tile's attention (post-loop) ----
    {
        int tp  = bid + GRID * (ntiles - 1);
        int rbp = tp / NHEAD;
        do_attention(x, out, qbuf, kbuf, vbuf,
                     rbp * 128, (tp - rbp * NHEAD) * 64, tid, epib, false);
    }
}

// ================= launch =================
typedef CUresult (*PFN_encodeTiled)(CUtensorMap*, CUtensorMapDataType, cuuint32_t,
                                    void*, const cuuint64_t*, const cuuint64_t*,
                                    const cuuint32_t*, const cuuint32_t*,
                                    CUtensorMapInterleave, CUtensorMapSwizzle,
                                    CUtensorMapL2promotion, CUtensorMapFloatOOBfill);

extern "C" void kernel_launch(void* const* d_in, const int* in_sizes, int n_in,
                              void* d_out, int out_size) {
    const float* x     = (const float*)d_in[0];
    const float* Wq    = (const float*)d_in[1];
    const float* Wk    = (const float*)d_in[2];
    const float* Wv    = (const float*)d_in[3];
    const float* gamma = (const float*)d_in[4];
    const float* beta  = (const float*)d_in[5];
    float* out = (float*)d_out;

    PFN_encodeTiled enc = nullptr;
    cudaDriverEntryPointQueryResult qr;
    cudaGetDriverEntryPoint("cuTensorMapEncodeTiled", (void**)&enc,
                            cudaEnableDefault, &qr);

    void* xn_ptr = nullptr;
    void* w_ptr  = nullptr;
    cudaGetSymbolAddress(&xn_ptr, g_xn2);
    cudaGetSymbolAddress(&w_ptr,  g_w2);

    const cuuint32_t es[2] = {1, 1};
    CUtensorMap mA, mW[3];
    {
        cuuint64_t dims[2] = {DDIM, BS};
        cuuint64_t strd[1] = {DDIM * 2};
        cuuint32_t box[2]  = {64, 128};
        enc(&mA, CU_TENSOR_MAP_DATA_TYPE_FLOAT16, 2, xn_ptr, dims, strd, box, es,
            CU_TENSOR_MAP_INTERLEAVE_NONE, CU_TENSOR_MAP_SWIZZLE_128B,
            CU_TENSOR_MAP_L2_PROMOTION_L2_128B, CU_TENSOR_MAP_FLOAT_OOB_FILL_NONE);
    }
    for (int m = 0; m < 3; m++) {
        cuuint64_t dims[2] = {DDIM, DDIM};
        cuuint64_t strd[1] = {DDIM * 2};
        cuuint32_t box[2]  = {64, 64};
        void* base = (char*)w_ptr + (size_t)m * DDIM * DDIM * 2;
        enc(&mW[m], CU_TENSOR_MAP_DATA_TYPE_FLOAT16, 2, base, dims, strd, box, es,
            CU_TENSOR_MAP_INTERLEAVE_NONE, CU_TENSOR_MAP_SWIZZLE_128B,
            CU_TENSOR_MAP_L2_PROMOTION_L2_128B, CU_TENSOR_MAP_FLOAT_OOB_FILL_NONE);
    }

    cudaFuncSetAttribute(attn_kernel, cudaFuncAttributeMaxDynamicSharedMemorySize, SMEM_BYTES);

    prep_kernel<<<576 + BS / 8, 256>>>(x, Wq, Wk, Wv, gamma, beta);
    attn_kernel<<<GRID, NTHREADS, SMEM_BYTES>>>(x, out, mA, mW[0], mW[1], mW[2]);
}